// round 10
// baseline (speedup 1.0000x reference)
#include <cuda_runtime.h>
#include <cuda_bf16.h>
#include <float.h>
#include <stdint.h>

// ---------------------------------------------------------------------------
// MVCNN: ragged max-pool -> 3-layer MLP.
// GEMMs via mma.sync.m16n8k16 (bf16 hi/lo split, f32 acc).
// R10: warp tile m32 x n64 (CTA m64 x n256), k32 stages -> 23% less smem
//      traffic per output. Single-barrier loop. W half-prefetch (regs<=128).
// ---------------------------------------------------------------------------

#define BATCH 64
#define DIM   4096
#define VIEWS 256
#define OUTN  1000

__device__ __align__(256) __nv_bfloat16 g_actH[BATCH * DIM];
__device__ __align__(256) __nv_bfloat16 g_actL[BATCH * DIM];
__device__ __align__(256) float g_part[16][DIM * BATCH];  // [ksplit][feat][batch]

// ---------------------------------------------------------------------------
// helpers
// ---------------------------------------------------------------------------
__device__ __forceinline__ uint32_t smem_u32(const void* p) {
    uint32_t a;
    asm("{ .reg .u64 t; cvta.to.shared.u64 t, %1; cvt.u32.u64 %0, t; }"
        : "=r"(a) : "l"(p));
    return a;
}
__device__ __forceinline__ void cp16(uint32_t dst, const void* src) {
    asm volatile("cp.async.cg.shared.global [%0], [%1], 16;"
                 :: "r"(dst), "l"(src));
}
__device__ __forceinline__ void cp_commit() {
    asm volatile("cp.async.commit_group;" ::: "memory");
}
template<int N> __device__ __forceinline__ void cp_wait() {
    asm volatile("cp.async.wait_group %0;" :: "n"(N) : "memory");
}
__device__ __forceinline__ void ldsm4(uint32_t* r, uint32_t a) {
    asm volatile("ldmatrix.sync.aligned.m8n8.x4.shared.b16 {%0,%1,%2,%3}, [%4];"
        : "=r"(r[0]), "=r"(r[1]), "=r"(r[2]), "=r"(r[3]) : "r"(a));
}
__device__ __forceinline__ void ldsm4t(uint32_t* r, uint32_t a) {
    asm volatile("ldmatrix.sync.aligned.m8n8.x4.trans.shared.b16 {%0,%1,%2,%3}, [%4];"
        : "=r"(r[0]), "=r"(r[1]), "=r"(r[2]), "=r"(r[3]) : "r"(a));
}
__device__ __forceinline__ void mma16816(float* c, const uint32_t* a,
                                         uint32_t b0, uint32_t b1) {
    asm volatile(
        "mma.sync.aligned.m16n8k16.row.col.f32.bf16.bf16.f32 "
        "{%0,%1,%2,%3}, {%4,%5,%6,%7}, {%8,%9}, {%0,%1,%2,%3};"
        : "+f"(c[0]), "+f"(c[1]), "+f"(c[2]), "+f"(c[3])
        : "r"(a[0]), "r"(a[1]), "r"(a[2]), "r"(a[3]), "r"(b0), "r"(b1));
}
__device__ __forceinline__ void cvt_hilo(float4 f, uint32_t& h01, uint32_t& h23,
                                         uint32_t& l01, uint32_t& l23) {
    asm("cvt.rn.satfinite.bf16x2.f32 %0, %1, %2;" : "=r"(h01) : "f"(f.y), "f"(f.x));
    asm("cvt.rn.satfinite.bf16x2.f32 %0, %1, %2;" : "=r"(h23) : "f"(f.w), "f"(f.z));
    float l0 = f.x - __uint_as_float(h01 << 16);
    float l1 = f.y - __uint_as_float(h01 & 0xffff0000u);
    float l2 = f.z - __uint_as_float(h23 << 16);
    float l3 = f.w - __uint_as_float(h23 & 0xffff0000u);
    asm("cvt.rn.satfinite.bf16x2.f32 %0, %1, %2;" : "=r"(l01) : "f"(l1), "f"(l0));
    asm("cvt.rn.satfinite.bf16x2.f32 %0, %1, %2;" : "=r"(l23) : "f"(l3), "f"(l2));
}

// ---------------------------------------------------------------------------
// Ragged max-pool -> bf16 hi/lo activations  act[batch][feat]
// ---------------------------------------------------------------------------
__global__ void pool_kernel(const float* __restrict__ x,
                            const float* __restrict__ xa,
                            const int*   __restrict__ lens,
                            __nv_bfloat16* __restrict__ actH,
                            __nv_bfloat16* __restrict__ actL)
{
    int warp = (blockIdx.x * blockDim.x + threadIdx.x) >> 5;
    int lane = threadIdx.x & 31;
    if (warp >= BATCH * DIM) return;
    int b = warp >> 12;
    int d = warp & 4095;

    const float* src = (d < 2048)
        ? (x  + ((size_t)(b * 2048 + d)        ) * VIEWS)
        : (xa + ((size_t)(b * 2048 + (d - 2048))) * VIEWS);

    int len = lens[b];
    len = max(1, min(len, VIEWS));

    float m = -FLT_MAX;
    for (int v0 = lane * 4; v0 < len; v0 += 128) {
        float4 v = *reinterpret_cast<const float4*>(src + v0);
        m = fmaxf(m, v.x);
        if (v0 + 1 < len) m = fmaxf(m, v.y);
        if (v0 + 2 < len) m = fmaxf(m, v.z);
        if (v0 + 3 < len) m = fmaxf(m, v.w);
    }
    #pragma unroll
    for (int o = 16; o; o >>= 1)
        m = fmaxf(m, __shfl_xor_sync(0xffffffffu, m, o));

    if (lane == 0) {
        __nv_bfloat16 h = __float2bfloat16(m);
        actH[warp] = h;
        actL[warp] = __float2bfloat16(m - __bfloat162float(h));
    }
}

// ---------------------------------------------------------------------------
// GEMM: part[ks][feat][batch] = act[64,kchunk] @ W[kchunk, NT-tile]
//   NTW = warp n-width (64 or 16). CTA tile = m64 x (4*NTW). k-step 32.
//   256 threads = 8 warps (2m x 4n), warp m32 x nNTW.
//   smem/stage: WH|WL (32 rows x NT*2 B each) + AH|AL (64 rows x 128 B each)
// ---------------------------------------------------------------------------
template<int NTW>
__global__ void __launch_bounds__(256) gemm_mma(
    const float* __restrict__ W, int N,
    const __nv_bfloat16* __restrict__ actH,
    const __nv_bfloat16* __restrict__ actL,
    float* __restrict__ partBase, int kchunk)
{
    constexpr int NT  = NTW * 4;
    constexpr int RB  = NT * 2;          // W smem row bytes
    constexpr int WB1 = 32 * RB;         // one polarity W stage
    constexpr int OFF_WL = WB1;
    constexpr int OFF_AH = 2 * WB1;
    constexpr int OFF_AL = 2 * WB1 + 8192;
    constexpr int STG = 2 * WB1 + 16384;
    constexpr int NJ  = NT / 32;         // float4 per thread for W stage
    constexpr int NJ0 = NJ / 2;          // prefetched half
    constexpr int NJ1 = NJ - NJ0;
    constexpr int NTT = NTW / 16;        // n16 tiles per warp

    extern __shared__ char smraw[];
    const uint32_t s0 = (smem_u32(smraw) + 1023) & ~1023u;
    const int tid = threadIdx.x;
    const int warp = tid >> 5, lane = tid & 31;
    const int warpM = warp & 1;
    const int warpN = warp >> 1;
    const int n0 = blockIdx.x * NT;
    const int kb = blockIdx.y * kchunk;
    float* part = partBase + (size_t)blockIdx.y * (DIM * BATCH);
    const int nst = kchunk >> 5;

    // W fp32 load: 8 threads per k-row (32 rows), NT/8 floats per thread
    const int wk = tid >> 3;
    const int wn = (tid & 7) * (NT / 8);
    const float* wgp = W + (size_t)(kb + wk) * N + n0 + wn;
    const uint32_t wswz = (uint32_t)(wk & 7) << 4;
    const uint32_t wsrow = (uint32_t)wk * RB;

    // A cp.async: 4 threads per m-row, 1 x 16B per polarity (k32 in 64B rows,
    // padded to 128B rows for swizzle reuse)
    const int am = tid >> 2;
    const int akc = (tid & 3) * 8;       // k elems
    const __nv_bfloat16* agpH = actH + (size_t)am * DIM + kb + akc;
    const __nv_bfloat16* agpL = actL + (size_t)am * DIM + kb + akc;
    const uint32_t aoff = (uint32_t)am * 128
                        + (((uint32_t)(akc * 2)) ^ ((uint32_t)(am & 7) << 4));

    const uint32_t arow = (lane & 7) + ((lane >> 3) & 1) * 8;
    const uint32_t ak2  = ((lane >> 4) & 1) * 16;
    const uint32_t aswz = (uint32_t)(lane & 7) << 4;

    const uint32_t brow  = (lane & 7) + ((lane >> 3) & 1) * 8;
    const uint32_t bhalf = ((lane >> 4) & 1) * 8;

    float acc[2][2 * NTT][4];
    #pragma unroll
    for (int i = 0; i < 2; ++i)
        #pragma unroll
        for (int j = 0; j < 2 * NTT; ++j)
            #pragma unroll
            for (int q = 0; q < 4; ++q) acc[i][j][q] = 0.f;

    float4 w0[NJ0];   // prefetched half of next W stage

    auto ldWj = [&](int s, int j) -> float4 {
        const float* p = wgp + (size_t)(s * 32) * N + j * 4;
        int col = n0 + wn + j * 4;
        if (col + 3 < N) return *reinterpret_cast<const float4*>(p);
        float4 v;
        v.x = (col + 0 < N) ? p[0] : 0.f;
        v.y = (col + 1 < N) ? p[1] : 0.f;
        v.z = (col + 2 < N) ? p[2] : 0.f;
        v.w = (col + 3 < N) ? p[3] : 0.f;
        return v;
    };
    auto loadW0 = [&](int s) {
        #pragma unroll
        for (int j = 0; j < NJ0; ++j) w0[j] = ldWj(s, j);
    };
    auto stWj = [&](uint32_t base, int j, float4 f) {
        uint32_t off = ((uint32_t)((wn + j * 4) * 2)) ^ wswz;
        uint32_t h01, h23, l01, l23;
        cvt_hilo(f, h01, h23, l01, l23);
        asm volatile("st.shared.v2.b32 [%0], {%1,%2};"
                     :: "r"(base + off), "r"(h01), "r"(h23));
        asm volatile("st.shared.v2.b32 [%0], {%1,%2};"
                     :: "r"(base + OFF_WL + off), "r"(l01), "r"(l23));
    };
    auto storeW = [&](int s, int buf) {
        const uint32_t base = s0 + buf * STG + wsrow;
        float4 w1[NJ1];
        #pragma unroll
        for (int j = 0; j < NJ1; ++j) w1[j] = ldWj(s, NJ0 + j);   // LDG 2nd half
        #pragma unroll
        for (int j = 0; j < NJ0; ++j) stWj(base, j, w0[j]);       // covers latency
        #pragma unroll
        for (int j = 0; j < NJ1; ++j) stWj(base, NJ0 + j, w1[j]);
    };
    auto issueA = [&](int s, int buf) {
        const uint32_t base = s0 + buf * STG;
        cp16(base + OFF_AH + aoff, agpH + s * 32);
        cp16(base + OFF_AL + aoff, agpL + s * 32);
        cp_commit();
    };
    auto compute = [&](int buf) {
        const uint32_t base = s0 + buf * STG;
        #pragma unroll
        for (int ks = 0; ks < 2; ++ks) {
            const uint32_t kx = (uint32_t)(ks * 32 + ak2) ^ aswz;
            uint32_t ah[2][4], al[2][4];
            #pragma unroll
            for (int mt = 0; mt < 2; ++mt) {
                const uint32_t ar = (uint32_t)(warpM * 32 + mt * 16 + arow) * 128 + kx;
                ldsm4(ah[mt], base + OFF_AH + ar);
                ldsm4(al[mt], base + OFF_AL + ar);
            }
            #pragma unroll
            for (int nt = 0; nt < NTT; ++nt) {
                uint32_t bcol = ((uint32_t)((warpN * NTW + nt * 16 + bhalf) * 2))
                              ^ ((uint32_t)(lane & 7) << 4);
                uint32_t boff = (uint32_t)(ks * 16 + brow) * RB + bcol;
                uint32_t bh[4], bl[4];
                ldsm4t(bh, base + boff);
                ldsm4t(bl, base + OFF_WL + boff);
                #pragma unroll
                for (int mt = 0; mt < 2; ++mt) {
                    mma16816(acc[mt][nt * 2 + 0], ah[mt], bh[0], bh[1]);
                    mma16816(acc[mt][nt * 2 + 1], ah[mt], bh[2], bh[3]);
                    mma16816(acc[mt][nt * 2 + 0], al[mt], bh[0], bh[1]);
                    mma16816(acc[mt][nt * 2 + 1], al[mt], bh[2], bh[3]);
                    mma16816(acc[mt][nt * 2 + 0], ah[mt], bl[0], bl[1]);
                    mma16816(acc[mt][nt * 2 + 1], ah[mt], bl[2], bl[3]);
                }
            }
        }
    };

    // ---- single-barrier pipeline (R9-proven) ----
    issueA(0, 0);
    loadW0(0);
    for (int s = 0; s < nst; ++s) {
        const int buf = s & 1;
        storeW(s, buf);
        if (s + 1 < nst) loadW0(s + 1);
        cp_wait<0>();
        __syncthreads();
        if (s + 1 < nst) issueA(s + 1, buf ^ 1);
        compute(buf);
    }

    // epilogue: scatter f32 partials  part[feat*64 + batch]
    const int g = lane >> 2, tg = lane & 3;
    #pragma unroll
    for (int mt = 0; mt < 2; ++mt)
        #pragma unroll
        for (int j = 0; j < 2 * NTT; ++j) {
            int feat = n0 + warpN * NTW + j * 8 + tg * 2;
            int bat  = warpM * 32 + mt * 16 + g;
            float* p = part + (size_t)feat * 64 + bat;
            p[0]      = acc[mt][j][0];
            p[64]     = acc[mt][j][1];
            p[8]      = acc[mt][j][2];
            p[64 + 8] = acc[mt][j][3];
        }
}

// ---------------------------------------------------------------------------
// Reduce K-splits + bias + relu -> next-layer bf16 hi/lo activations
// ---------------------------------------------------------------------------
__global__ void reduce_bias_relu(const float* __restrict__ bias,
                                 __nv_bfloat16* __restrict__ actH,
                                 __nv_bfloat16* __restrict__ actL)
{
    int idx = blockIdx.x * 256 + threadIdx.x;   // 64*4096
    int n = idx >> 12;       // batch
    int m = idx & 4095;      // feat
    float s = bias[m];
    #pragma unroll
    for (int z = 0; z < 16; ++z) s += g_part[z][m * 64 + n];
    s = fmaxf(s, 0.f);
    __nv_bfloat16 h = __float2bfloat16(s);
    actH[idx] = h;
    actL[idx] = __float2bfloat16(s - __bfloat162float(h));
}

__global__ void reduce_out(const float* __restrict__ b3,
                           float* __restrict__ out)
{
    int idx = blockIdx.x * 256 + threadIdx.x;
    if (idx >= BATCH * OUTN) return;
    int n = idx / OUTN;      // batch
    int m = idx - n * OUTN;  // feat
    float s = b3[m];
    #pragma unroll
    for (int z = 0; z < 16; ++z) s += g_part[z][m * 64 + n];
    out[idx] = s;
}

// ---------------------------------------------------------------------------
// launch
// ---------------------------------------------------------------------------
extern "C" void kernel_launch(void* const* d_in, const int* in_sizes, int n_in,
                              void* d_out, int out_size)
{
    const float* x    = (const float*)d_in[0];
    const float* xa   = (const float*)d_in[1];
    const int*   lens = (const int*)  d_in[2];
    const float* w1   = (const float*)d_in[3];
    const float* b1   = (const float*)d_in[4];
    const float* w2   = (const float*)d_in[5];
    const float* b2   = (const float*)d_in[6];
    const float* w3   = (const float*)d_in[7];
    const float* b3   = (const float*)d_in[8];
    float* out = (float*)d_out;

    __nv_bfloat16 *actH, *actL;
    float* part;
    cudaGetSymbolAddress((void**)&actH, g_actH);
    cudaGetSymbolAddress((void**)&actL, g_actL);
    cudaGetSymbolAddress((void**)&part, g_part);

    const int SMEM256 = 2 * (2 * 32 * 512 + 16384) + 1024;   // 99328
    const int SMEM64  = 2 * (2 * 32 * 128 + 16384) + 1024;   // 50176
    cudaFuncSetAttribute(gemm_mma<64>,
                         cudaFuncAttributeMaxDynamicSharedMemorySize, SMEM256);
    cudaFuncSetAttribute(gemm_mma<16>,
                         cudaFuncAttributeMaxDynamicSharedMemorySize, SMEM64);

    // 1) pool -> act hi/lo
    {
        int warps = BATCH * DIM;
        int blocks = (warps * 32 + 255) / 256;
        pool_kernel<<<blocks, 256>>>(x, xa, lens, actH, actL);
    }
    // 2) layer 1: 16 n256-tiles x ksplit 16 (kchunk 256, 8 k32-stages)
    gemm_mma<64><<<dim3(16, 16), 256, SMEM256>>>(w1, DIM, actH, actL, part, 256);
    reduce_bias_relu<<<1024, 256>>>(b1, actH, actL);
    // 3) layer 2
    gemm_mma<64><<<dim3(16, 16), 256, SMEM256>>>(w2, DIM, actH, actL, part, 256);
    reduce_bias_relu<<<1024, 256>>>(b2, actH, actL);
    // 4) layer 3: 16 n64-tiles x ksplit 16 (kchunk 256, 8 k32-stages)
    gemm_mma<16><<<dim3(16, 16), 256, SMEM64>>>(w3, OUTN, actH, actL, part, 256);
    reduce_out<<<(BATCH * OUTN + 255) / 256, 256>>>(b3, out);
}

// round 11
// speedup vs baseline: 1.2824x; 1.2824x over previous
#include <cuda_runtime.h>
#include <cuda_bf16.h>
#include <float.h>
#include <stdint.h>

// ---------------------------------------------------------------------------
// MVCNN: ragged max-pool -> 3-layer MLP.
// GEMMs via mma.sync.m16n8k16 (bf16 hi/lo split, f32 acc).
// R11 = R9 (proven) + coalesced smem-transpose reduce kernels
//       (old reduces had 8x sector amplification on g_part reads).
// ---------------------------------------------------------------------------

#define BATCH 64
#define DIM   4096
#define VIEWS 256
#define OUTN  1000

__device__ __align__(256) __nv_bfloat16 g_actH[BATCH * DIM];
__device__ __align__(256) __nv_bfloat16 g_actL[BATCH * DIM];
__device__ __align__(256) float g_part[16][DIM * BATCH];  // [ksplit][feat][batch]

// ---------------------------------------------------------------------------
// helpers
// ---------------------------------------------------------------------------
__device__ __forceinline__ uint32_t smem_u32(const void* p) {
    uint32_t a;
    asm("{ .reg .u64 t; cvta.to.shared.u64 t, %1; cvt.u32.u64 %0, t; }"
        : "=r"(a) : "l"(p));
    return a;
}
__device__ __forceinline__ void cp16(uint32_t dst, const void* src) {
    asm volatile("cp.async.cg.shared.global [%0], [%1], 16;"
                 :: "r"(dst), "l"(src));
}
__device__ __forceinline__ void cp_commit() {
    asm volatile("cp.async.commit_group;" ::: "memory");
}
template<int N> __device__ __forceinline__ void cp_wait() {
    asm volatile("cp.async.wait_group %0;" :: "n"(N) : "memory");
}
__device__ __forceinline__ void ldsm4(uint32_t* r, uint32_t a) {
    asm volatile("ldmatrix.sync.aligned.m8n8.x4.shared.b16 {%0,%1,%2,%3}, [%4];"
        : "=r"(r[0]), "=r"(r[1]), "=r"(r[2]), "=r"(r[3]) : "r"(a));
}
__device__ __forceinline__ void ldsm4t(uint32_t* r, uint32_t a) {
    asm volatile("ldmatrix.sync.aligned.m8n8.x4.trans.shared.b16 {%0,%1,%2,%3}, [%4];"
        : "=r"(r[0]), "=r"(r[1]), "=r"(r[2]), "=r"(r[3]) : "r"(a));
}
__device__ __forceinline__ void mma16816(float* c, const uint32_t* a,
                                         uint32_t b0, uint32_t b1) {
    asm volatile(
        "mma.sync.aligned.m16n8k16.row.col.f32.bf16.bf16.f32 "
        "{%0,%1,%2,%3}, {%4,%5,%6,%7}, {%8,%9}, {%0,%1,%2,%3};"
        : "+f"(c[0]), "+f"(c[1]), "+f"(c[2]), "+f"(c[3])
        : "r"(a[0]), "r"(a[1]), "r"(a[2]), "r"(a[3]), "r"(b0), "r"(b1));
}

// ---------------------------------------------------------------------------
// Ragged max-pool -> bf16 hi/lo activations  act[batch][feat]
// ---------------------------------------------------------------------------
__global__ void pool_kernel(const float* __restrict__ x,
                            const float* __restrict__ xa,
                            const int*   __restrict__ lens,
                            __nv_bfloat16* __restrict__ actH,
                            __nv_bfloat16* __restrict__ actL)
{
    int warp = (blockIdx.x * blockDim.x + threadIdx.x) >> 5;
    int lane = threadIdx.x & 31;
    if (warp >= BATCH * DIM) return;
    int b = warp >> 12;
    int d = warp & 4095;

    const float* src = (d < 2048)
        ? (x  + ((size_t)(b * 2048 + d)        ) * VIEWS)
        : (xa + ((size_t)(b * 2048 + (d - 2048))) * VIEWS);

    int len = lens[b];
    len = max(1, min(len, VIEWS));

    float m = -FLT_MAX;
    for (int v0 = lane * 4; v0 < len; v0 += 128) {
        float4 v = *reinterpret_cast<const float4*>(src + v0);
        m = fmaxf(m, v.x);
        if (v0 + 1 < len) m = fmaxf(m, v.y);
        if (v0 + 2 < len) m = fmaxf(m, v.z);
        if (v0 + 3 < len) m = fmaxf(m, v.w);
    }
    #pragma unroll
    for (int o = 16; o; o >>= 1)
        m = fmaxf(m, __shfl_xor_sync(0xffffffffu, m, o));

    if (lane == 0) {
        __nv_bfloat16 h = __float2bfloat16(m);
        actH[warp] = h;
        actL[warp] = __float2bfloat16(m - __bfloat162float(h));
    }
}

// ---------------------------------------------------------------------------
// GEMM template: part[ks][feat][batch] = act[64,kchunk] @ W[kchunk, NT-tile]
//   grid (ceil(N/NT), KSPLIT), 256 threads = 8 warps (2m x 4n)
//   NT=128: warp m32 x n32 ; NT=64: warp m32 x n16
//   smem: 2 stages x { WH | WL | AH 8K | AL 8K }
// ---------------------------------------------------------------------------
template<int NT>
__global__ void __launch_bounds__(256) gemm_mma(
    const float* __restrict__ W, int N,
    const __nv_bfloat16* __restrict__ actH,
    const __nv_bfloat16* __restrict__ actL,
    float* __restrict__ partBase, int kchunk)
{
    constexpr int RB     = NT * 2;          // W smem row bytes
    constexpr int WBYTES = 64 * RB;         // one polarity W tile
    constexpr int OFF_WL = WBYTES;
    constexpr int OFF_AH = 2 * WBYTES;
    constexpr int OFF_AL = 2 * WBYTES + 8192;
    constexpr int STG    = 2 * WBYTES + 16384;
    constexpr int NJ     = NT / 16;         // float4/thread for W tile
    constexpr int WNW    = NT / 4;          // warp n width
    constexpr int NTT    = NT / 64;         // n16 ldsm tiles per warp

    extern __shared__ char smraw[];
    const uint32_t s0 = (smem_u32(smraw) + 1023) & ~1023u;
    const int tid = threadIdx.x;
    const int warp = tid >> 5, lane = tid & 31;
    const int warpM = warp & 1;
    const int warpN = warp >> 1;
    const int n0 = blockIdx.x * NT;
    const int kb = blockIdx.y * kchunk;
    float* part = partBase + (size_t)blockIdx.y * (DIM * BATCH);
    const int nst = kchunk >> 6;

    // W fp32 load: 4 threads per k-row
    const int wk = tid >> 2;
    const int wn = (tid & 3) * WNW;
    const float* wgp = W + (size_t)(kb + wk) * N + n0 + wn;
    const uint32_t wswz = (uint32_t)(wk & 7) << 4;
    const uint32_t wsrow = (uint32_t)wk * RB;

    // A cp.async: 4 threads per m-row, 2 x 16B each
    const int am = tid >> 2;
    const int akb = (tid & 3) * 16;
    const __nv_bfloat16* agpH = actH + (size_t)am * DIM + kb + akb;
    const __nv_bfloat16* agpL = actL + (size_t)am * DIM + kb + akb;
    uint32_t aoffc[2];
    #pragma unroll
    for (int c = 0; c < 2; ++c)
        aoffc[c] = (uint32_t)am * 128
                 + (((uint32_t)(akb * 2 + c * 16)) ^ ((uint32_t)(am & 7) << 4));

    const uint32_t arow = (lane & 7) + ((lane >> 3) & 1) * 8;
    const uint32_t ak2  = ((lane >> 4) & 1) * 16;
    const uint32_t aswz = (uint32_t)(lane & 7) << 4;

    const uint32_t brow  = (lane & 7) + ((lane >> 3) & 1) * 8;
    const uint32_t bhalf = ((lane >> 4) & 1) * 8;

    float acc[2][2 * NTT][4];
    #pragma unroll
    for (int i = 0; i < 2; ++i)
        #pragma unroll
        for (int j = 0; j < 2 * NTT; ++j)
            #pragma unroll
            for (int q = 0; q < 4; ++q) acc[i][j][q] = 0.f;

    float4 wreg[NJ];

    auto loadW = [&](int s) {
        const float* p = wgp + (size_t)s * 64 * N;
        #pragma unroll
        for (int j = 0; j < NJ; ++j) {
            int col = n0 + wn + j * 4;
            if (col + 3 < N) {
                wreg[j] = *reinterpret_cast<const float4*>(p + j * 4);
            } else {
                float4 v;
                v.x = (col + 0 < N) ? p[j * 4 + 0] : 0.f;
                v.y = (col + 1 < N) ? p[j * 4 + 1] : 0.f;
                v.z = (col + 2 < N) ? p[j * 4 + 2] : 0.f;
                v.w = (col + 3 < N) ? p[j * 4 + 3] : 0.f;
                wreg[j] = v;
            }
        }
    };
    auto storeW = [&](int buf) {
        const uint32_t base = s0 + buf * STG + wsrow;
        #pragma unroll
        for (int j = 0; j < NJ; ++j) {
            uint32_t off = ((uint32_t)((wn + j * 4) * 2)) ^ wswz;
            float4 f = wreg[j];
            uint32_t h01, h23, l01, l23;
            asm("cvt.rn.satfinite.bf16x2.f32 %0, %1, %2;" : "=r"(h01) : "f"(f.y), "f"(f.x));
            asm("cvt.rn.satfinite.bf16x2.f32 %0, %1, %2;" : "=r"(h23) : "f"(f.w), "f"(f.z));
            float l0 = f.x - __uint_as_float(h01 << 16);
            float l1 = f.y - __uint_as_float(h01 & 0xffff0000u);
            float l2 = f.z - __uint_as_float(h23 << 16);
            float l3 = f.w - __uint_as_float(h23 & 0xffff0000u);
            asm("cvt.rn.satfinite.bf16x2.f32 %0, %1, %2;" : "=r"(l01) : "f"(l1), "f"(l0));
            asm("cvt.rn.satfinite.bf16x2.f32 %0, %1, %2;" : "=r"(l23) : "f"(l3), "f"(l2));
            asm volatile("st.shared.v2.b32 [%0], {%1,%2};"
                         :: "r"(base + off), "r"(h01), "r"(h23));
            asm volatile("st.shared.v2.b32 [%0], {%1,%2};"
                         :: "r"(base + OFF_WL + off), "r"(l01), "r"(l23));
        }
    };
    auto issueA = [&](int s, int buf) {
        const uint32_t base = s0 + buf * STG;
        #pragma unroll
        for (int c = 0; c < 2; ++c) {
            cp16(base + OFF_AH + aoffc[c], agpH + s * 64 + c * 8);
            cp16(base + OFF_AL + aoffc[c], agpL + s * 64 + c * 8);
        }
        cp_commit();
    };
    auto compute = [&](int buf) {
        const uint32_t base = s0 + buf * STG;
        #pragma unroll
        for (int ks = 0; ks < 4; ++ks) {
            uint32_t bh[NTT][4], bl[NTT][4];
            #pragma unroll
            for (int nt = 0; nt < NTT; ++nt) {
                uint32_t bcol = ((uint32_t)((warpN * WNW + nt * 16 + bhalf) * 2))
                              ^ ((uint32_t)(lane & 7) << 4);
                uint32_t boff = (uint32_t)(ks * 16 + brow) * RB + bcol;
                ldsm4t(bh[nt], base + boff);
                ldsm4t(bl[nt], base + OFF_WL + boff);
            }
            const uint32_t kx = (uint32_t)(ks * 32 + ak2) ^ aswz;
            #pragma unroll
            for (int mt = 0; mt < 2; ++mt) {
                const uint32_t arow0 = (uint32_t)(warpM * 32 + mt * 16) * 128
                                     + arow * 128 + kx;
                uint32_t ah[4], al[4];
                ldsm4(ah, base + OFF_AH + arow0);
                ldsm4(al, base + OFF_AL + arow0);
                #pragma unroll
                for (int nt = 0; nt < NTT; ++nt) {
                    mma16816(acc[mt][nt * 2 + 0], ah, bh[nt][0], bh[nt][1]);
                    mma16816(acc[mt][nt * 2 + 1], ah, bh[nt][2], bh[nt][3]);
                    mma16816(acc[mt][nt * 2 + 0], al, bh[nt][0], bh[nt][1]);
                    mma16816(acc[mt][nt * 2 + 1], al, bh[nt][2], bh[nt][3]);
                    mma16816(acc[mt][nt * 2 + 0], ah, bl[nt][0], bl[nt][1]);
                    mma16816(acc[mt][nt * 2 + 1], ah, bl[nt][2], bl[nt][3]);
                }
            }
        }
    };

    // ---- single-barrier pipeline (R9-proven) ----
    issueA(0, 0);
    loadW(0);
    for (int s = 0; s < nst; ++s) {
        const int buf = s & 1;
        storeW(buf);
        if (s + 1 < nst) loadW(s + 1);
        cp_wait<0>();
        __syncthreads();
        if (s + 1 < nst) issueA(s + 1, buf ^ 1);
        compute(buf);
    }

    // epilogue: scatter f32 partials  part[feat*64 + batch]
    const int g = lane >> 2, tg = lane & 3;
    #pragma unroll
    for (int mt = 0; mt < 2; ++mt)
        #pragma unroll
        for (int nt = 0; nt < 2 * NTT; ++nt) {
            int feat = n0 + warpN * WNW + nt * 8 + tg * 2;
            int bat  = warpM * 32 + mt * 16 + g;
            float* p = part + (size_t)feat * 64 + bat;
            p[0]      = acc[mt][nt][0];
            p[64]     = acc[mt][nt][1];
            p[8]      = acc[mt][nt][2];
            p[64 + 8] = acc[mt][nt][3];
        }
}

// ---------------------------------------------------------------------------
// Coalesced transpose-reduce: K-splits + bias + relu -> bf16 hi/lo acts.
// Tile = 16 feats x 64 batches. Read phase: threads walk batch (contiguous
// in g_part). Write phase: threads walk feat (contiguous in act).
// ---------------------------------------------------------------------------
__global__ void __launch_bounds__(256) reduce_bias_relu_t(
    const float* __restrict__ bias,
    __nv_bfloat16* __restrict__ actH,
    __nv_bfloat16* __restrict__ actL)
{
    __shared__ __nv_bfloat16 tH[16][66], tL[16][66];
    const int t = threadIdx.x;
    const int mb = blockIdx.x * 16;      // grid 256 covers 4096 feats

    {   // read: consecutive t -> consecutive batch n (coalesced)
        const int n  = t & 63;
        const int ml = t >> 6;           // 0..3
        #pragma unroll
        for (int j = 0; j < 4; ++j) {
            int mloc = ml * 4 + j;
            int m = mb + mloc;
            float s = bias[m];
            #pragma unroll
            for (int z = 0; z < 8; ++z)
                s += g_part[z][(size_t)m * 64 + n];
            s = fmaxf(s, 0.f);
            __nv_bfloat16 h = __float2bfloat16(s);
            tH[mloc][n] = h;
            tL[mloc][n] = __float2bfloat16(s - __bfloat162float(h));
        }
    }
    __syncthreads();
    {   // write: consecutive t -> consecutive feat m (coalesced)
        const int m2 = t & 15;
        const int nl = t >> 4;           // 0..15
        #pragma unroll
        for (int j = 0; j < 4; ++j) {
            int n2 = nl * 4 + j;
            size_t o = (size_t)n2 * DIM + mb + m2;
            actH[o] = tH[m2][n2];
            actL[o] = tL[m2][n2];
        }
    }
}

// out = sum of 16 partials + b3 ; tile = 8 feats x 64 batches, grid 125
__global__ void __launch_bounds__(256) reduce_out_t(
    const float* __restrict__ b3,
    float* __restrict__ out)
{
    __shared__ float tO[8][66];
    const int t = threadIdx.x;
    const int mb = blockIdx.x * 8;       // 125 * 8 = 1000 exact

    #pragma unroll
    for (int i = t; i < 512; i += 256) { // read: n contiguous
        int mloc = i >> 6;
        int n = i & 63;
        int m = mb + mloc;
        float s = b3[m];
        #pragma unroll
        for (int z = 0; z < 16; ++z)
            s += g_part[z][(size_t)m * 64 + n];
        tO[mloc][n] = s;
    }
    __syncthreads();
    #pragma unroll
    for (int i = t; i < 512; i += 256) { // write: m contiguous
        int mloc = i & 7;
        int n2 = i >> 3;
        out[(size_t)n2 * OUTN + mb + mloc] = tO[mloc][n2];
    }
}

// ---------------------------------------------------------------------------
// launch
// ---------------------------------------------------------------------------
extern "C" void kernel_launch(void* const* d_in, const int* in_sizes, int n_in,
                              void* d_out, int out_size)
{
    const float* x    = (const float*)d_in[0];
    const float* xa   = (const float*)d_in[1];
    const int*   lens = (const int*)  d_in[2];
    const float* w1   = (const float*)d_in[3];
    const float* b1   = (const float*)d_in[4];
    const float* w2   = (const float*)d_in[5];
    const float* b2   = (const float*)d_in[6];
    const float* w3   = (const float*)d_in[7];
    const float* b3   = (const float*)d_in[8];
    float* out = (float*)d_out;

    __nv_bfloat16 *actH, *actL;
    float* part;
    cudaGetSymbolAddress((void**)&actH, g_actH);
    cudaGetSymbolAddress((void**)&actL, g_actL);
    cudaGetSymbolAddress((void**)&part, g_part);

    const int SMEM128 = 2 * (2 * 64 * 256 + 16384) + 1024;   // 99328
    const int SMEM64  = 2 * (2 * 64 * 128 + 16384) + 1024;   // 66560
    cudaFuncSetAttribute(gemm_mma<128>,
                         cudaFuncAttributeMaxDynamicSharedMemorySize, SMEM128);
    cudaFuncSetAttribute(gemm_mma<64>,
                         cudaFuncAttributeMaxDynamicSharedMemorySize, SMEM64);

    // 1) pool -> act hi/lo
    {
        int warps = BATCH * DIM;
        int blocks = (warps * 32 + 255) / 256;
        pool_kernel<<<blocks, 256>>>(x, xa, lens, actH, actL);
    }
    // 2) layer 1: 32 n-tiles x ksplit 8 (kchunk 512, 8 stages)
    gemm_mma<128><<<dim3(32, 8), 256, SMEM128>>>(w1, DIM, actH, actL, part, 512);
    reduce_bias_relu_t<<<256, 256>>>(b1, actH, actL);
    // 3) layer 2
    gemm_mma<128><<<dim3(32, 8), 256, SMEM128>>>(w2, DIM, actH, actL, part, 512);
    reduce_bias_relu_t<<<256, 256>>>(b2, actH, actL);
    // 4) layer 3: N=1000 -> 16 n64-tiles x ksplit 16 (kchunk 256, 4 stages)
    gemm_mma<64><<<dim3(16, 16), 256, SMEM64>>>(w3, OUTN, actH, actL, part, 256);
    reduce_out_t<<<125, 256>>>(b3, out);
}

// round 12
// speedup vs baseline: 1.3810x; 1.0769x over previous
#include <cuda_runtime.h>
#include <cuda_bf16.h>
#include <float.h>
#include <stdint.h>

// ---------------------------------------------------------------------------
// MVCNN: ragged max-pool -> 3-layer MLP.
// GEMMs via mma.sync.m16n8k16 (bf16 hi/lo split, f32 acc).
// R12 = R11 (proven 133.2us) + high-MLP pool (4 rows/warp, 8 outstanding
//       loads/thread) + compile-time stage count (full pipeline unroll).
// ---------------------------------------------------------------------------

#define BATCH 64
#define DIM   4096
#define VIEWS 256
#define OUTN  1000

__device__ __align__(256) __nv_bfloat16 g_actH[BATCH * DIM];
__device__ __align__(256) __nv_bfloat16 g_actL[BATCH * DIM];
__device__ __align__(256) float g_part[16][DIM * BATCH];  // [ksplit][feat][batch]

// ---------------------------------------------------------------------------
// helpers
// ---------------------------------------------------------------------------
__device__ __forceinline__ uint32_t smem_u32(const void* p) {
    uint32_t a;
    asm("{ .reg .u64 t; cvta.to.shared.u64 t, %1; cvt.u32.u64 %0, t; }"
        : "=r"(a) : "l"(p));
    return a;
}
__device__ __forceinline__ void cp16(uint32_t dst, const void* src) {
    asm volatile("cp.async.cg.shared.global [%0], [%1], 16;"
                 :: "r"(dst), "l"(src));
}
__device__ __forceinline__ void cp_commit() {
    asm volatile("cp.async.commit_group;" ::: "memory");
}
template<int N> __device__ __forceinline__ void cp_wait() {
    asm volatile("cp.async.wait_group %0;" :: "n"(N) : "memory");
}
__device__ __forceinline__ void ldsm4(uint32_t* r, uint32_t a) {
    asm volatile("ldmatrix.sync.aligned.m8n8.x4.shared.b16 {%0,%1,%2,%3}, [%4];"
        : "=r"(r[0]), "=r"(r[1]), "=r"(r[2]), "=r"(r[3]) : "r"(a));
}
__device__ __forceinline__ void ldsm4t(uint32_t* r, uint32_t a) {
    asm volatile("ldmatrix.sync.aligned.m8n8.x4.trans.shared.b16 {%0,%1,%2,%3}, [%4];"
        : "=r"(r[0]), "=r"(r[1]), "=r"(r[2]), "=r"(r[3]) : "r"(a));
}
__device__ __forceinline__ void mma16816(float* c, const uint32_t* a,
                                         uint32_t b0, uint32_t b1) {
    asm volatile(
        "mma.sync.aligned.m16n8k16.row.col.f32.bf16.bf16.f32 "
        "{%0,%1,%2,%3}, {%4,%5,%6,%7}, {%8,%9}, {%0,%1,%2,%3};"
        : "+f"(c[0]), "+f"(c[1]), "+f"(c[2]), "+f"(c[3])
        : "r"(a[0]), "r"(a[1]), "r"(a[2]), "r"(a[3]), "r"(b0), "r"(b1));
}

// ---------------------------------------------------------------------------
// Ragged max-pool -> bf16 hi/lo activations  act[batch][feat]
// R12: warp handles 4 rows; lane = (row-in-group = lane>>3, slice = lane&7).
// 8 independent predicated float4 loads per thread (MLP 8), 128B coalesced
// chunks per row per step. Max-reduce via 3 intra-8-lane shfls.
// ---------------------------------------------------------------------------
__global__ void pool_kernel(const float* __restrict__ x,
                            const float* __restrict__ xa,
                            const int*   __restrict__ lens,
                            __nv_bfloat16* __restrict__ actH,
                            __nv_bfloat16* __restrict__ actL)
{
    const int gw   = (blockIdx.x * blockDim.x + threadIdx.x) >> 5;
    const int lane = threadIdx.x & 31;
    const int rg   = lane >> 3;          // row within group of 4
    const int sub  = lane & 7;           // 8-lane slice within row
    const int row  = gw * 4 + rg;
    if (row >= BATCH * DIM) return;
    const int b = row >> 12;
    const int d = row & 4095;

    const float* src = (d < 2048)
        ? (x  + ((size_t)(b * 2048 + d)        ) * VIEWS)
        : (xa + ((size_t)(b * 2048 + (d - 2048))) * VIEWS);

    int len = lens[b];
    len = max(1, min(len, VIEWS));

    float m = -FLT_MAX;
    #pragma unroll
    for (int i = 0; i < 8; ++i) {
        const int v0 = sub * 4 + i * 32;
        if (v0 < len) {
            float4 v = *reinterpret_cast<const float4*>(src + v0);
            m = fmaxf(m, v.x);
            if (v0 + 1 < len) m = fmaxf(m, v.y);
            if (v0 + 2 < len) m = fmaxf(m, v.z);
            if (v0 + 3 < len) m = fmaxf(m, v.w);
        }
    }
    #pragma unroll
    for (int o = 4; o; o >>= 1)
        m = fmaxf(m, __shfl_xor_sync(0xffffffffu, m, o));

    if (sub == 0) {
        __nv_bfloat16 h = __float2bfloat16(m);
        actH[row] = h;
        actL[row] = __float2bfloat16(m - __bfloat162float(h));
    }
}

// ---------------------------------------------------------------------------
// GEMM template: part[ks][feat][batch] = act[64,NST*64] @ W[NST*64, NT-tile]
//   grid (ceil(N/NT), KSPLIT), 256 threads = 8 warps (2m x 4n)
//   NT=128: warp m32 x n32 ; NT=64: warp m32 x n16.  NST = k64 stages.
// ---------------------------------------------------------------------------
template<int NT, int NST>
__global__ void __launch_bounds__(256) gemm_mma(
    const float* __restrict__ W, int N,
    const __nv_bfloat16* __restrict__ actH,
    const __nv_bfloat16* __restrict__ actL,
    float* __restrict__ partBase)
{
    constexpr int KCH    = NST * 64;
    constexpr int RB     = NT * 2;          // W smem row bytes
    constexpr int WBYTES = 64 * RB;         // one polarity W tile
    constexpr int OFF_WL = WBYTES;
    constexpr int OFF_AH = 2 * WBYTES;
    constexpr int OFF_AL = 2 * WBYTES + 8192;
    constexpr int STG    = 2 * WBYTES + 16384;
    constexpr int NJ     = NT / 16;         // float4/thread for W tile
    constexpr int WNW    = NT / 4;          // warp n width
    constexpr int NTT    = NT / 64;         // n16 ldsm tiles per warp

    extern __shared__ char smraw[];
    const uint32_t s0 = (smem_u32(smraw) + 1023) & ~1023u;
    const int tid = threadIdx.x;
    const int warp = tid >> 5, lane = tid & 31;
    const int warpM = warp & 1;
    const int warpN = warp >> 1;
    const int n0 = blockIdx.x * NT;
    const int kb = blockIdx.y * KCH;
    float* part = partBase + (size_t)blockIdx.y * (DIM * BATCH);

    // W fp32 load: 4 threads per k-row
    const int wk = tid >> 2;
    const int wn = (tid & 3) * WNW;
    const float* wgp = W + (size_t)(kb + wk) * N + n0 + wn;
    const uint32_t wswz = (uint32_t)(wk & 7) << 4;
    const uint32_t wsrow = (uint32_t)wk * RB;

    // A cp.async: 4 threads per m-row, 2 x 16B each
    const int am = tid >> 2;
    const int akb = (tid & 3) * 16;
    const __nv_bfloat16* agpH = actH + (size_t)am * DIM + kb + akb;
    const __nv_bfloat16* agpL = actL + (size_t)am * DIM + kb + akb;
    uint32_t aoffc[2];
    #pragma unroll
    for (int c = 0; c < 2; ++c)
        aoffc[c] = (uint32_t)am * 128
                 + (((uint32_t)(akb * 2 + c * 16)) ^ ((uint32_t)(am & 7) << 4));

    const uint32_t arow = (lane & 7) + ((lane >> 3) & 1) * 8;
    const uint32_t ak2  = ((lane >> 4) & 1) * 16;
    const uint32_t aswz = (uint32_t)(lane & 7) << 4;

    const uint32_t brow  = (lane & 7) + ((lane >> 3) & 1) * 8;
    const uint32_t bhalf = ((lane >> 4) & 1) * 8;

    float acc[2][2 * NTT][4];
    #pragma unroll
    for (int i = 0; i < 2; ++i)
        #pragma unroll
        for (int j = 0; j < 2 * NTT; ++j)
            #pragma unroll
            for (int q = 0; q < 4; ++q) acc[i][j][q] = 0.f;

    float4 wreg[NJ];

    auto loadW = [&](int s) {
        const float* p = wgp + (size_t)s * 64 * N;
        #pragma unroll
        for (int j = 0; j < NJ; ++j) {
            int col = n0 + wn + j * 4;
            if (col + 3 < N) {
                wreg[j] = *reinterpret_cast<const float4*>(p + j * 4);
            } else {
                float4 v;
                v.x = (col + 0 < N) ? p[j * 4 + 0] : 0.f;
                v.y = (col + 1 < N) ? p[j * 4 + 1] : 0.f;
                v.z = (col + 2 < N) ? p[j * 4 + 2] : 0.f;
                v.w = (col + 3 < N) ? p[j * 4 + 3] : 0.f;
                wreg[j] = v;
            }
        }
    };
    auto storeW = [&](int buf) {
        const uint32_t base = s0 + buf * STG + wsrow;
        #pragma unroll
        for (int j = 0; j < NJ; ++j) {
            uint32_t off = ((uint32_t)((wn + j * 4) * 2)) ^ wswz;
            float4 f = wreg[j];
            uint32_t h01, h23, l01, l23;
            asm("cvt.rn.satfinite.bf16x2.f32 %0, %1, %2;" : "=r"(h01) : "f"(f.y), "f"(f.x));
            asm("cvt.rn.satfinite.bf16x2.f32 %0, %1, %2;" : "=r"(h23) : "f"(f.w), "f"(f.z));
            float l0 = f.x - __uint_as_float(h01 << 16);
            float l1 = f.y - __uint_as_float(h01 & 0xffff0000u);
            float l2 = f.z - __uint_as_float(h23 << 16);
            float l3 = f.w - __uint_as_float(h23 & 0xffff0000u);
            asm("cvt.rn.satfinite.bf16x2.f32 %0, %1, %2;" : "=r"(l01) : "f"(l1), "f"(l0));
            asm("cvt.rn.satfinite.bf16x2.f32 %0, %1, %2;" : "=r"(l23) : "f"(l3), "f"(l2));
            asm volatile("st.shared.v2.b32 [%0], {%1,%2};"
                         :: "r"(base + off), "r"(h01), "r"(h23));
            asm volatile("st.shared.v2.b32 [%0], {%1,%2};"
                         :: "r"(base + OFF_WL + off), "r"(l01), "r"(l23));
        }
    };
    auto issueA = [&](int s, int buf) {
        const uint32_t base = s0 + buf * STG;
        #pragma unroll
        for (int c = 0; c < 2; ++c) {
            cp16(base + OFF_AH + aoffc[c], agpH + s * 64 + c * 8);
            cp16(base + OFF_AL + aoffc[c], agpL + s * 64 + c * 8);
        }
        cp_commit();
    };
    auto compute = [&](int buf) {
        const uint32_t base = s0 + buf * STG;
        #pragma unroll
        for (int ks = 0; ks < 4; ++ks) {
            uint32_t bh[NTT][4], bl[NTT][4];
            #pragma unroll
            for (int nt = 0; nt < NTT; ++nt) {
                uint32_t bcol = ((uint32_t)((warpN * WNW + nt * 16 + bhalf) * 2))
                              ^ ((uint32_t)(lane & 7) << 4);
                uint32_t boff = (uint32_t)(ks * 16 + brow) * RB + bcol;
                ldsm4t(bh[nt], base + boff);
                ldsm4t(bl[nt], base + OFF_WL + boff);
            }
            const uint32_t kx = (uint32_t)(ks * 32 + ak2) ^ aswz;
            #pragma unroll
            for (int mt = 0; mt < 2; ++mt) {
                const uint32_t arow0 = (uint32_t)(warpM * 32 + mt * 16) * 128
                                     + arow * 128 + kx;
                uint32_t ah[4], al[4];
                ldsm4(ah, base + OFF_AH + arow0);
                ldsm4(al, base + OFF_AL + arow0);
                #pragma unroll
                for (int nt = 0; nt < NTT; ++nt) {
                    mma16816(acc[mt][nt * 2 + 0], ah, bh[nt][0], bh[nt][1]);
                    mma16816(acc[mt][nt * 2 + 1], ah, bh[nt][2], bh[nt][3]);
                    mma16816(acc[mt][nt * 2 + 0], al, bh[nt][0], bh[nt][1]);
                    mma16816(acc[mt][nt * 2 + 1], al, bh[nt][2], bh[nt][3]);
                    mma16816(acc[mt][nt * 2 + 0], ah, bl[nt][0], bl[nt][1]);
                    mma16816(acc[mt][nt * 2 + 1], ah, bl[nt][2], bl[nt][3]);
                }
            }
        }
    };

    // ---- single-barrier pipeline (R9-proven), fully unrolled over NST ----
    issueA(0, 0);
    loadW(0);
    #pragma unroll
    for (int s = 0; s < NST; ++s) {
        const int buf = s & 1;
        storeW(buf);
        if (s + 1 < NST) loadW(s + 1);
        cp_wait<0>();
        __syncthreads();
        if (s + 1 < NST) issueA(s + 1, buf ^ 1);
        compute(buf);
    }

    // epilogue: scatter f32 partials  part[feat*64 + batch]
    const int g = lane >> 2, tg = lane & 3;
    #pragma unroll
    for (int mt = 0; mt < 2; ++mt)
        #pragma unroll
        for (int nt = 0; nt < 2 * NTT; ++nt) {
            int feat = n0 + warpN * WNW + nt * 8 + tg * 2;
            int bat  = warpM * 32 + mt * 16 + g;
            float* p = part + (size_t)feat * 64 + bat;
            p[0]      = acc[mt][nt][0];
            p[64]     = acc[mt][nt][1];
            p[8]      = acc[mt][nt][2];
            p[64 + 8] = acc[mt][nt][3];
        }
}

// ---------------------------------------------------------------------------
// Coalesced transpose-reduce: K-splits + bias + relu -> bf16 hi/lo acts.
// ---------------------------------------------------------------------------
__global__ void __launch_bounds__(256) reduce_bias_relu_t(
    const float* __restrict__ bias,
    __nv_bfloat16* __restrict__ actH,
    __nv_bfloat16* __restrict__ actL)
{
    __shared__ __nv_bfloat16 tH[16][66], tL[16][66];
    const int t = threadIdx.x;
    const int mb = blockIdx.x * 16;

    {
        const int n  = t & 63;
        const int ml = t >> 6;
        #pragma unroll
        for (int j = 0; j < 4; ++j) {
            int mloc = ml * 4 + j;
            int m = mb + mloc;
            float s = bias[m];
            #pragma unroll
            for (int z = 0; z < 8; ++z)
                s += g_part[z][(size_t)m * 64 + n];
            s = fmaxf(s, 0.f);
            __nv_bfloat16 h = __float2bfloat16(s);
            tH[mloc][n] = h;
            tL[mloc][n] = __float2bfloat16(s - __bfloat162float(h));
        }
    }
    __syncthreads();
    {
        const int m2 = t & 15;
        const int nl = t >> 4;
        #pragma unroll
        for (int j = 0; j < 4; ++j) {
            int n2 = nl * 4 + j;
            size_t o = (size_t)n2 * DIM + mb + m2;
            actH[o] = tH[m2][n2];
            actL[o] = tL[m2][n2];
        }
    }
}

__global__ void __launch_bounds__(256) reduce_out_t(
    const float* __restrict__ b3,
    float* __restrict__ out)
{
    __shared__ float tO[8][66];
    const int t = threadIdx.x;
    const int mb = blockIdx.x * 8;

    #pragma unroll
    for (int i = t; i < 512; i += 256) {
        int mloc = i >> 6;
        int n = i & 63;
        int m = mb + mloc;
        float s = b3[m];
        #pragma unroll
        for (int z = 0; z < 16; ++z)
            s += g_part[z][(size_t)m * 64 + n];
        tO[mloc][n] = s;
    }
    __syncthreads();
    #pragma unroll
    for (int i = t; i < 512; i += 256) {
        int mloc = i & 7;
        int n2 = i >> 3;
        out[(size_t)n2 * OUTN + mb + mloc] = tO[mloc][n2];
    }
}

// ---------------------------------------------------------------------------
// launch
// ---------------------------------------------------------------------------
extern "C" void kernel_launch(void* const* d_in, const int* in_sizes, int n_in,
                              void* d_out, int out_size)
{
    const float* x    = (const float*)d_in[0];
    const float* xa   = (const float*)d_in[1];
    const int*   lens = (const int*)  d_in[2];
    const float* w1   = (const float*)d_in[3];
    const float* b1   = (const float*)d_in[4];
    const float* w2   = (const float*)d_in[5];
    const float* b2   = (const float*)d_in[6];
    const float* w3   = (const float*)d_in[7];
    const float* b3   = (const float*)d_in[8];
    float* out = (float*)d_out;

    __nv_bfloat16 *actH, *actL;
    float* part;
    cudaGetSymbolAddress((void**)&actH, g_actH);
    cudaGetSymbolAddress((void**)&actL, g_actL);
    cudaGetSymbolAddress((void**)&part, g_part);

    const int SMEM128 = 2 * (2 * 64 * 256 + 16384) + 1024;   // 99328
    const int SMEM64  = 2 * (2 * 64 * 128 + 16384) + 1024;   // 66560
    cudaFuncSetAttribute((void*)gemm_mma<128, 8>,
                         cudaFuncAttributeMaxDynamicSharedMemorySize, SMEM128);
    cudaFuncSetAttribute((void*)gemm_mma<64, 4>,
                         cudaFuncAttributeMaxDynamicSharedMemorySize, SMEM64);

    // 1) pool -> act hi/lo (4 rows per warp, MLP 8)
    {
        int warps = (BATCH * DIM) / 4;              // 65536
        int blocks = (warps * 32 + 255) / 256;      // 8192
        pool_kernel<<<blocks, 256>>>(x, xa, lens, actH, actL);
    }
    // 2) layer 1: 32 n-tiles x ksplit 8 (kchunk 512, 8 stages)
    gemm_mma<128, 8><<<dim3(32, 8), 256, SMEM128>>>(w1, DIM, actH, actL, part);
    reduce_bias_relu_t<<<256, 256>>>(b1, actH, actL);
    // 3) layer 2
    gemm_mma<128, 8><<<dim3(32, 8), 256, SMEM128>>>(w2, DIM, actH, actL, part);
    reduce_bias_relu_t<<<256, 256>>>(b2, actH, actL);
    // 4) layer 3: N=1000 -> 16 n64-tiles x ksplit 16 (kchunk 256, 4 stages)
    gemm_mma<64, 4><<<dim3(16, 16), 256, SMEM64>>>(w3, OUTN, actH, actL, part);
    reduce_out_t<<<125, 256>>>(b3, out);
}

// round 13
// speedup vs baseline: 1.4536x; 1.0526x over previous
#include <cuda_runtime.h>
#include <cuda_bf16.h>
#include <float.h>
#include <stdint.h>

// ---------------------------------------------------------------------------
// MVCNN: ragged max-pool -> 3-layer MLP.
// GEMMs via mma.sync.m16n8k16 (bf16 hi/lo split, f32 acc).
// R13 = R12 + L1/L2 GEMM restaged at k32 (stage 32KB, wreg 8 regs,
//       __launch_bounds__(256,3) -> 3 CTAs/SM, 24 warps). Same traffic/k.
// ---------------------------------------------------------------------------

#define BATCH 64
#define DIM   4096
#define VIEWS 256
#define OUTN  1000

__device__ __align__(256) __nv_bfloat16 g_actH[BATCH * DIM];
__device__ __align__(256) __nv_bfloat16 g_actL[BATCH * DIM];
__device__ __align__(256) float g_part[16][DIM * BATCH];  // [ksplit][feat][batch]

// ---------------------------------------------------------------------------
// helpers
// ---------------------------------------------------------------------------
__device__ __forceinline__ uint32_t smem_u32(const void* p) {
    uint32_t a;
    asm("{ .reg .u64 t; cvta.to.shared.u64 t, %1; cvt.u32.u64 %0, t; }"
        : "=r"(a) : "l"(p));
    return a;
}
__device__ __forceinline__ void cp16(uint32_t dst, const void* src) {
    asm volatile("cp.async.cg.shared.global [%0], [%1], 16;"
                 :: "r"(dst), "l"(src));
}
__device__ __forceinline__ void cp_commit() {
    asm volatile("cp.async.commit_group;" ::: "memory");
}
template<int N> __device__ __forceinline__ void cp_wait() {
    asm volatile("cp.async.wait_group %0;" :: "n"(N) : "memory");
}
__device__ __forceinline__ void ldsm4(uint32_t* r, uint32_t a) {
    asm volatile("ldmatrix.sync.aligned.m8n8.x4.shared.b16 {%0,%1,%2,%3}, [%4];"
        : "=r"(r[0]), "=r"(r[1]), "=r"(r[2]), "=r"(r[3]) : "r"(a));
}
__device__ __forceinline__ void ldsm4t(uint32_t* r, uint32_t a) {
    asm volatile("ldmatrix.sync.aligned.m8n8.x4.trans.shared.b16 {%0,%1,%2,%3}, [%4];"
        : "=r"(r[0]), "=r"(r[1]), "=r"(r[2]), "=r"(r[3]) : "r"(a));
}
__device__ __forceinline__ void mma16816(float* c, const uint32_t* a,
                                         uint32_t b0, uint32_t b1) {
    asm volatile(
        "mma.sync.aligned.m16n8k16.row.col.f32.bf16.bf16.f32 "
        "{%0,%1,%2,%3}, {%4,%5,%6,%7}, {%8,%9}, {%0,%1,%2,%3};"
        : "+f"(c[0]), "+f"(c[1]), "+f"(c[2]), "+f"(c[3])
        : "r"(a[0]), "r"(a[1]), "r"(a[2]), "r"(a[3]), "r"(b0), "r"(b1));
}
__device__ __forceinline__ void stW_hilo(uint32_t baseH, uint32_t baseL,
                                         uint32_t off, float4 f) {
    uint32_t h01, h23, l01, l23;
    asm("cvt.rn.satfinite.bf16x2.f32 %0, %1, %2;" : "=r"(h01) : "f"(f.y), "f"(f.x));
    asm("cvt.rn.satfinite.bf16x2.f32 %0, %1, %2;" : "=r"(h23) : "f"(f.w), "f"(f.z));
    float l0 = f.x - __uint_as_float(h01 << 16);
    float l1 = f.y - __uint_as_float(h01 & 0xffff0000u);
    float l2 = f.z - __uint_as_float(h23 << 16);
    float l3 = f.w - __uint_as_float(h23 & 0xffff0000u);
    asm("cvt.rn.satfinite.bf16x2.f32 %0, %1, %2;" : "=r"(l01) : "f"(l1), "f"(l0));
    asm("cvt.rn.satfinite.bf16x2.f32 %0, %1, %2;" : "=r"(l23) : "f"(l3), "f"(l2));
    asm volatile("st.shared.v2.b32 [%0], {%1,%2};"
                 :: "r"(baseH + off), "r"(h01), "r"(h23));
    asm volatile("st.shared.v2.b32 [%0], {%1,%2};"
                 :: "r"(baseL + off), "r"(l01), "r"(l23));
}

// ---------------------------------------------------------------------------
// Ragged max-pool -> bf16 hi/lo activations  act[batch][feat]  (R12-proven)
// ---------------------------------------------------------------------------
__global__ void pool_kernel(const float* __restrict__ x,
                            const float* __restrict__ xa,
                            const int*   __restrict__ lens,
                            __nv_bfloat16* __restrict__ actH,
                            __nv_bfloat16* __restrict__ actL)
{
    const int gw   = (blockIdx.x * blockDim.x + threadIdx.x) >> 5;
    const int lane = threadIdx.x & 31;
    const int rg   = lane >> 3;
    const int sub  = lane & 7;
    const int row  = gw * 4 + rg;
    if (row >= BATCH * DIM) return;
    const int b = row >> 12;
    const int d = row & 4095;

    const float* src = (d < 2048)
        ? (x  + ((size_t)(b * 2048 + d)        ) * VIEWS)
        : (xa + ((size_t)(b * 2048 + (d - 2048))) * VIEWS);

    int len = lens[b];
    len = max(1, min(len, VIEWS));

    float m = -FLT_MAX;
    #pragma unroll
    for (int i = 0; i < 8; ++i) {
        const int v0 = sub * 4 + i * 32;
        if (v0 < len) {
            float4 v = *reinterpret_cast<const float4*>(src + v0);
            m = fmaxf(m, v.x);
            if (v0 + 1 < len) m = fmaxf(m, v.y);
            if (v0 + 2 < len) m = fmaxf(m, v.z);
            if (v0 + 3 < len) m = fmaxf(m, v.w);
        }
    }
    #pragma unroll
    for (int o = 4; o; o >>= 1)
        m = fmaxf(m, __shfl_xor_sync(0xffffffffu, m, o));

    if (sub == 0) {
        __nv_bfloat16 h = __float2bfloat16(m);
        actH[row] = h;
        actL[row] = __float2bfloat16(m - __bfloat162float(h));
    }
}

// ---------------------------------------------------------------------------
// R13 GEMM (layers 1/2): k32 stages, NT=128, 3 CTAs/SM.
//   grid (32, 8): n128-tiles x ksplit 8; kchunk 512 -> NST=16 k32-stages.
//   smem/stage: WH 8K | WL 8K | AH 8K | AL 8K  (A rows 128B, low-k half used)
// ---------------------------------------------------------------------------
#define STG32     32768
#define O32_WL    8192
#define O32_AH    16384
#define O32_AL    24576
#define SMEM_K32  (2 * STG32 + 1024)

__global__ void __launch_bounds__(256, 3) gemm_k32(
    const float* __restrict__ W,
    const __nv_bfloat16* __restrict__ actH,
    const __nv_bfloat16* __restrict__ actL,
    float* __restrict__ partBase)
{
    constexpr int N   = DIM;
    constexpr int NST = 16;

    extern __shared__ char smraw[];
    const uint32_t s0 = (smem_u32(smraw) + 1023) & ~1023u;
    const int tid = threadIdx.x;
    const int warp = tid >> 5, lane = tid & 31;
    const int warpM = warp & 1;
    const int warpN = warp >> 1;
    const int n0 = blockIdx.x * 128;
    const int kb = blockIdx.y * 512;
    float* part = partBase + (size_t)blockIdx.y * (DIM * BATCH);

    // W fp32 load: 8 threads per k-row (32 rows), 16 floats each
    const int wk = tid >> 3;
    const int wn = (tid & 7) * 16;
    const float* wgp = W + (size_t)(kb + wk) * N + n0 + wn;
    const uint32_t wswz = (uint32_t)(wk & 7) << 4;
    const uint32_t wsrow = (uint32_t)wk * 256;

    // A cp.async: 4 threads per m-row, 1 x 16B per polarity
    const int am = tid >> 2;
    const int akc = (tid & 3) * 8;                    // k elems
    const __nv_bfloat16* agpH = actH + (size_t)am * DIM + kb + akc;
    const __nv_bfloat16* agpL = actL + (size_t)am * DIM + kb + akc;
    const uint32_t aoff = (uint32_t)am * 128
                        + (((uint32_t)(akc * 2)) ^ ((uint32_t)(am & 7) << 4));

    const uint32_t arow = (lane & 7) + ((lane >> 3) & 1) * 8;
    const uint32_t ak2  = ((lane >> 4) & 1) * 16;
    const uint32_t aswz = (uint32_t)(lane & 7) << 4;

    const uint32_t brow  = (lane & 7) + ((lane >> 3) & 1) * 8;
    const uint32_t bhalf = ((lane >> 4) & 1) * 8;

    float acc[2][4][4];
    #pragma unroll
    for (int i = 0; i < 2; ++i)
        #pragma unroll
        for (int j = 0; j < 4; ++j)
            #pragma unroll
            for (int q = 0; q < 4; ++q) acc[i][j][q] = 0.f;

    float4 w0[2];    // prefetched half of next W stage (8 regs)

    auto ldWj = [&](int s, int j) -> float4 {
        return *reinterpret_cast<const float4*>(
            wgp + (size_t)(s * 32) * N + j * 4);
    };
    auto loadW0 = [&](int s) {
        w0[0] = ldWj(s, 0);
        w0[1] = ldWj(s, 1);
    };
    auto storeW = [&](int s, int buf) {
        const uint32_t bH = s0 + buf * STG32 + wsrow;
        const uint32_t bL = bH + O32_WL;
        float4 w2 = ldWj(s, 2);
        float4 w3 = ldWj(s, 3);
        stW_hilo(bH, bL, ((uint32_t)((wn + 0) * 2)) ^ wswz, w0[0]);
        stW_hilo(bH, bL, ((uint32_t)((wn + 4) * 2)) ^ wswz, w0[1]);
        stW_hilo(bH, bL, ((uint32_t)((wn + 8) * 2)) ^ wswz, w2);
        stW_hilo(bH, bL, ((uint32_t)((wn + 12) * 2)) ^ wswz, w3);
    };
    auto issueA = [&](int s, int buf) {
        const uint32_t base = s0 + buf * STG32;
        cp16(base + O32_AH + aoff, agpH + s * 32);
        cp16(base + O32_AL + aoff, agpL + s * 32);
        cp_commit();
    };
    auto compute = [&](int buf) {
        const uint32_t base = s0 + buf * STG32;
        #pragma unroll
        for (int ks = 0; ks < 2; ++ks) {
            uint32_t bh[2][4], bl[2][4];
            #pragma unroll
            for (int nt = 0; nt < 2; ++nt) {
                uint32_t bcol = ((uint32_t)((warpN * 32 + nt * 16 + bhalf) * 2))
                              ^ ((uint32_t)(lane & 7) << 4);
                uint32_t boff = (uint32_t)(ks * 16 + brow) * 256 + bcol;
                ldsm4t(bh[nt], base + boff);
                ldsm4t(bl[nt], base + O32_WL + boff);
            }
            const uint32_t kx = (uint32_t)(ks * 32 + ak2) ^ aswz;
            #pragma unroll
            for (int mt = 0; mt < 2; ++mt) {
                const uint32_t ar = (uint32_t)(warpM * 32 + mt * 16 + arow) * 128
                                  + kx;
                uint32_t ah[4], al[4];
                ldsm4(ah, base + O32_AH + ar);
                ldsm4(al, base + O32_AL + ar);
                #pragma unroll
                for (int nt = 0; nt < 2; ++nt) {
                    mma16816(acc[mt][nt * 2 + 0], ah, bh[nt][0], bh[nt][1]);
                    mma16816(acc[mt][nt * 2 + 1], ah, bh[nt][2], bh[nt][3]);
                    mma16816(acc[mt][nt * 2 + 0], al, bh[nt][0], bh[nt][1]);
                    mma16816(acc[mt][nt * 2 + 1], al, bh[nt][2], bh[nt][3]);
                    mma16816(acc[mt][nt * 2 + 0], ah, bl[nt][0], bl[nt][1]);
                    mma16816(acc[mt][nt * 2 + 1], ah, bl[nt][2], bl[nt][3]);
                }
            }
        }
    };

    // ---- single-barrier pipeline (R9-proven ordering) ----
    issueA(0, 0);
    loadW0(0);
    #pragma unroll
    for (int s = 0; s < NST; ++s) {
        const int buf = s & 1;
        storeW(s, buf);
        if (s + 1 < NST) loadW0(s + 1);
        cp_wait<0>();
        __syncthreads();
        if (s + 1 < NST) issueA(s + 1, buf ^ 1);
        compute(buf);
    }

    // epilogue: scatter f32 partials  part[feat*64 + batch]
    const int g = lane >> 2, tg = lane & 3;
    #pragma unroll
    for (int mt = 0; mt < 2; ++mt)
        #pragma unroll
        for (int nt = 0; nt < 4; ++nt) {
            int feat = n0 + warpN * 32 + nt * 8 + tg * 2;
            int bat  = warpM * 32 + mt * 16 + g;
            float* p = part + (size_t)feat * 64 + bat;
            p[0]      = acc[mt][nt][0];
            p[64]     = acc[mt][nt][1];
            p[8]      = acc[mt][nt][2];
            p[64 + 8] = acc[mt][nt][3];
        }
}

// ---------------------------------------------------------------------------
// L3 GEMM (R12-proven): k64 stages, NT=64, NST=4
// ---------------------------------------------------------------------------
#define RB64      128
#define WB64      (64 * RB64)
#define O64_WL    WB64
#define O64_AH    (2 * WB64)
#define O64_AL    (2 * WB64 + 8192)
#define STG64     (2 * WB64 + 16384)
#define SMEM_K64  (2 * STG64 + 1024)

__global__ void __launch_bounds__(256) gemm_l3(
    const float* __restrict__ W, int N,
    const __nv_bfloat16* __restrict__ actH,
    const __nv_bfloat16* __restrict__ actL,
    float* __restrict__ partBase)
{
    constexpr int NST = 4;
    extern __shared__ char smraw[];
    const uint32_t s0 = (smem_u32(smraw) + 1023) & ~1023u;
    const int tid = threadIdx.x;
    const int warp = tid >> 5, lane = tid & 31;
    const int warpM = warp & 1;
    const int warpN = warp >> 1;
    const int n0 = blockIdx.x * 64;
    const int kb = blockIdx.y * 256;
    float* part = partBase + (size_t)blockIdx.y * (DIM * BATCH);

    const int wk = tid >> 2;
    const int wn = (tid & 3) * 16;
    const float* wgp = W + (size_t)(kb + wk) * N + n0 + wn;
    const uint32_t wswz = (uint32_t)(wk & 7) << 4;
    const uint32_t wsrow = (uint32_t)wk * RB64;

    const int am = tid >> 2;
    const int akb = (tid & 3) * 16;
    const __nv_bfloat16* agpH = actH + (size_t)am * DIM + kb + akb;
    const __nv_bfloat16* agpL = actL + (size_t)am * DIM + kb + akb;
    uint32_t aoffc[2];
    #pragma unroll
    for (int c = 0; c < 2; ++c)
        aoffc[c] = (uint32_t)am * 128
                 + (((uint32_t)(akb * 2 + c * 16)) ^ ((uint32_t)(am & 7) << 4));

    const uint32_t arow = (lane & 7) + ((lane >> 3) & 1) * 8;
    const uint32_t ak2  = ((lane >> 4) & 1) * 16;
    const uint32_t aswz = (uint32_t)(lane & 7) << 4;

    const uint32_t brow  = (lane & 7) + ((lane >> 3) & 1) * 8;
    const uint32_t bhalf = ((lane >> 4) & 1) * 8;

    float acc[2][2][4];
    #pragma unroll
    for (int i = 0; i < 2; ++i)
        #pragma unroll
        for (int j = 0; j < 2; ++j)
            #pragma unroll
            for (int q = 0; q < 4; ++q) acc[i][j][q] = 0.f;

    float4 wreg[4];

    auto loadW = [&](int s) {
        const float* p = wgp + (size_t)s * 64 * N;
        #pragma unroll
        for (int j = 0; j < 4; ++j) {
            int col = n0 + wn + j * 4;
            if (col + 3 < N) {
                wreg[j] = *reinterpret_cast<const float4*>(p + j * 4);
            } else {
                float4 v;
                v.x = (col + 0 < N) ? p[j * 4 + 0] : 0.f;
                v.y = (col + 1 < N) ? p[j * 4 + 1] : 0.f;
                v.z = (col + 2 < N) ? p[j * 4 + 2] : 0.f;
                v.w = (col + 3 < N) ? p[j * 4 + 3] : 0.f;
                wreg[j] = v;
            }
        }
    };
    auto storeW = [&](int buf) {
        const uint32_t bH = s0 + buf * STG64 + wsrow;
        const uint32_t bL = bH + O64_WL;
        #pragma unroll
        for (int j = 0; j < 4; ++j)
            stW_hilo(bH, bL, ((uint32_t)((wn + j * 4) * 2)) ^ wswz, wreg[j]);
    };
    auto issueA = [&](int s, int buf) {
        const uint32_t base = s0 + buf * STG64;
        #pragma unroll
        for (int c = 0; c < 2; ++c) {
            cp16(base + O64_AH + aoffc[c], agpH + s * 64 + c * 8);
            cp16(base + O64_AL + aoffc[c], agpL + s * 64 + c * 8);
        }
        cp_commit();
    };
    auto compute = [&](int buf) {
        const uint32_t base = s0 + buf * STG64;
        #pragma unroll
        for (int ks = 0; ks < 4; ++ks) {
            uint32_t bh[4], bl[4];
            uint32_t bcol = ((uint32_t)((warpN * 16 + bhalf) * 2))
                          ^ ((uint32_t)(lane & 7) << 4);
            uint32_t boff = (uint32_t)(ks * 16 + brow) * RB64 + bcol;
            ldsm4t(bh, base + boff);
            ldsm4t(bl, base + O64_WL + boff);
            const uint32_t kx = (uint32_t)(ks * 32 + ak2) ^ aswz;
            #pragma unroll
            for (int mt = 0; mt < 2; ++mt) {
                const uint32_t ar = (uint32_t)(warpM * 32 + mt * 16 + arow) * 128
                                  + kx;
                uint32_t ah[4], al[4];
                ldsm4(ah, base + O64_AH + ar);
                ldsm4(al, base + O64_AL + ar);
                mma16816(acc[mt][0], ah, bh[0], bh[1]);
                mma16816(acc[mt][1], ah, bh[2], bh[3]);
                mma16816(acc[mt][0], al, bh[0], bh[1]);
                mma16816(acc[mt][1], al, bh[2], bh[3]);
                mma16816(acc[mt][0], ah, bl[0], bl[1]);
                mma16816(acc[mt][1], ah, bl[2], bl[3]);
            }
        }
    };

    issueA(0, 0);
    loadW(0);
    #pragma unroll
    for (int s = 0; s < NST; ++s) {
        const int buf = s & 1;
        storeW(buf);
        if (s + 1 < NST) loadW(s + 1);
        cp_wait<0>();
        __syncthreads();
        if (s + 1 < NST) issueA(s + 1, buf ^ 1);
        compute(buf);
    }

    const int g = lane >> 2, tg = lane & 3;
    #pragma unroll
    for (int mt = 0; mt < 2; ++mt)
        #pragma unroll
        for (int nt = 0; nt < 2; ++nt) {
            int feat = n0 + warpN * 16 + nt * 8 + tg * 2;
            int bat  = warpM * 32 + mt * 16 + g;
            float* p = part + (size_t)feat * 64 + bat;
            p[0]      = acc[mt][nt][0];
            p[64]     = acc[mt][nt][1];
            p[8]      = acc[mt][nt][2];
            p[64 + 8] = acc[mt][nt][3];
        }
}

// ---------------------------------------------------------------------------
// Coalesced transpose-reduces (R11-proven)
// ---------------------------------------------------------------------------
__global__ void __launch_bounds__(256) reduce_bias_relu_t(
    const float* __restrict__ bias,
    __nv_bfloat16* __restrict__ actH,
    __nv_bfloat16* __restrict__ actL)
{
    __shared__ __nv_bfloat16 tH[16][66], tL[16][66];
    const int t = threadIdx.x;
    const int mb = blockIdx.x * 16;

    {
        const int n  = t & 63;
        const int ml = t >> 6;
        #pragma unroll
        for (int j = 0; j < 4; ++j) {
            int mloc = ml * 4 + j;
            int m = mb + mloc;
            float s = bias[m];
            #pragma unroll
            for (int z = 0; z < 8; ++z)
                s += g_part[z][(size_t)m * 64 + n];
            s = fmaxf(s, 0.f);
            __nv_bfloat16 h = __float2bfloat16(s);
            tH[mloc][n] = h;
            tL[mloc][n] = __float2bfloat16(s - __bfloat162float(h));
        }
    }
    __syncthreads();
    {
        const int m2 = t & 15;
        const int nl = t >> 4;
        #pragma unroll
        for (int j = 0; j < 4; ++j) {
            int n2 = nl * 4 + j;
            size_t o = (size_t)n2 * DIM + mb + m2;
            actH[o] = tH[m2][n2];
            actL[o] = tL[m2][n2];
        }
    }
}

__global__ void __launch_bounds__(256) reduce_out_t(
    const float* __restrict__ b3,
    float* __restrict__ out)
{
    __shared__ float tO[8][66];
    const int t = threadIdx.x;
    const int mb = blockIdx.x * 8;

    #pragma unroll
    for (int i = t; i < 512; i += 256) {
        int mloc = i >> 6;
        int n = i & 63;
        int m = mb + mloc;
        float s = b3[m];
        #pragma unroll
        for (int z = 0; z < 16; ++z)
            s += g_part[z][(size_t)m * 64 + n];
        tO[mloc][n] = s;
    }
    __syncthreads();
    #pragma unroll
    for (int i = t; i < 512; i += 256) {
        int mloc = i & 7;
        int n2 = i >> 3;
        out[(size_t)n2 * OUTN + mb + mloc] = tO[mloc][n2];
    }
}

// ---------------------------------------------------------------------------
// launch
// ---------------------------------------------------------------------------
extern "C" void kernel_launch(void* const* d_in, const int* in_sizes, int n_in,
                              void* d_out, int out_size)
{
    const float* x    = (const float*)d_in[0];
    const float* xa   = (const float*)d_in[1];
    const int*   lens = (const int*)  d_in[2];
    const float* w1   = (const float*)d_in[3];
    const float* b1   = (const float*)d_in[4];
    const float* w2   = (const float*)d_in[5];
    const float* b2   = (const float*)d_in[6];
    const float* w3   = (const float*)d_in[7];
    const float* b3   = (const float*)d_in[8];
    float* out = (float*)d_out;

    __nv_bfloat16 *actH, *actL;
    float* part;
    cudaGetSymbolAddress((void**)&actH, g_actH);
    cudaGetSymbolAddress((void**)&actL, g_actL);
    cudaGetSymbolAddress((void**)&part, g_part);

    cudaFuncSetAttribute(gemm_k32,
                         cudaFuncAttributeMaxDynamicSharedMemorySize, SMEM_K32);
    cudaFuncSetAttribute(gemm_l3,
                         cudaFuncAttributeMaxDynamicSharedMemorySize, SMEM_K64);

    // 1) pool -> act hi/lo (4 rows per warp, MLP 8)
    {
        int warps = (BATCH * DIM) / 4;
        int blocks = (warps * 32 + 255) / 256;
        pool_kernel<<<blocks, 256>>>(x, xa, lens, actH, actL);
    }
    // 2) layer 1: 32 n128-tiles x ksplit 8 (kchunk 512, 16 k32-stages)
    gemm_k32<<<dim3(32, 8), 256, SMEM_K32>>>(w1, actH, actL, part);
    reduce_bias_relu_t<<<256, 256>>>(b1, actH, actL);
    // 3) layer 2
    gemm_k32<<<dim3(32, 8), 256, SMEM_K32>>>(w2, actH, actL, part);
    reduce_bias_relu_t<<<256, 256>>>(b2, actH, actL);
    // 4) layer 3: 16 n64-tiles x ksplit 16 (kchunk 256, 4 k64-stages)
    gemm_l3<<<dim3(16, 16), 256, SMEM_K64>>>(w3, OUTN, actH, actL, part);
    reduce_out_t<<<125, 256>>>(b3, out);
}